// round 8
// baseline (speedup 1.0000x reference)
#include <cuda_runtime.h>
#include <math.h>

#define BB 4
#define NN 3000
#define CC 21
#define BN (BB*NN)

#define NGROUPS (BB*(CC-1))       // 80
#define THREADS 512
#define PREP_BLOCKS ((BN + THREADS - 1) / THREADS)   // 24
#define MAXM  320
#define WMAX  10

// ---------------------------------------------------------------------------
// device scratch (no allocations allowed)
// ---------------------------------------------------------------------------
__device__ signed char g_amax[BN];
__device__ float       g_score[BN];
__device__ float4      g_box[BN];
__device__ int         g_done;

// out layout (float32): [rounded BN*4][sigmoid BN][boxes BN*4][probs BN*C][keep BN]

// sbuf overlay (group path):
//   keys u64 [0,4096) | tlbr f4 [4096,9216) | area f [9216,10496) | sidx i32 [10496,11776)
//   keptw u32 [11776,11816)
//   fallback: keys u64 [0,32768)
__shared__ unsigned char sbuf[32768];
__shared__ unsigned int  maskbuf[MAXM * WMAX];
__shared__ int s_count;

__global__ void reset_kernel() { g_done = 0; }

__global__ void __launch_bounds__(THREADS)
fused_kernel(const float* __restrict__ nms_reg,
             const float* __restrict__ nms_cls,
             const float* __restrict__ rcnn_reg,
             const float* __restrict__ rcnn_cls,
             const unsigned int* __restrict__ red_raw,
             float* __restrict__ out)
{
    int tid  = threadIdx.x;
    int lane = tid & 31;

    float* o_keep = out + BN * 9 + BN * CC;

    if (blockIdx.x >= NGROUPS) {
        // ------------------------- prep (producer) -------------------------
        unsigned int wr = red_raw[0];
        float red = (wr < 0x10000u) ? (float)wr : __uint_as_float(wr);

        int idx = (blockIdx.x - NGROUPS) * THREADS + tid;
        if (idx < BN) {
            float* o_round = out;
            float* o_sig   = out + BN * 4;
            float* o_boxes = out + BN * 5;
            float* o_probs = out + BN * 9;

            float r0 = nms_reg[idx * 4 + 0];
            float r1 = nms_reg[idx * 4 + 1];
            float r2 = nms_reg[idx * 4 + 2];
            float r3 = nms_reg[idx * 4 + 3];
            float q0 = __fdiv_rn(floorf(__fmul_rn(r0, red)), red);
            float q1 = __fdiv_rn(floorf(__fmul_rn(r1, red)), red);
            float q2 = __fdiv_rn(ceilf(__fmul_rn(r2, red)), red);
            float q3 = __fdiv_rn(ceilf(__fmul_rn(r3, red)), red);
            o_round[idx * 4 + 0] = q0;
            o_round[idx * 4 + 1] = q1;
            o_round[idx * 4 + 2] = q2;
            o_round[idx * 4 + 3] = q3;

            float4 bx;
            bx.x = __fadd_rn(rcnn_reg[idx * 4 + 0], q0);
            bx.y = __fadd_rn(rcnn_reg[idx * 4 + 1], q1);
            bx.z = __fadd_rn(rcnn_reg[idx * 4 + 2], q2);
            bx.w = __fadd_rn(rcnn_reg[idx * 4 + 3], q3);
            o_boxes[idx * 4 + 0] = bx.x;
            o_boxes[idx * 4 + 1] = bx.y;
            o_boxes[idx * 4 + 2] = bx.z;
            o_boxes[idx * 4 + 3] = bx.w;
            g_box[idx] = bx;

            float s = nms_cls[idx];
            o_sig[idx] = 1.0f / (1.0f + expf(-s));

            float logit[CC];
            float m = -INFINITY;
            #pragma unroll
            for (int c = 0; c < CC; c++) {
                logit[c] = rcnn_cls[idx * CC + c];
                m = fmaxf(m, logit[c]);
            }
            float sum = 0.0f;
            float p[CC];
            #pragma unroll
            for (int c = 0; c < CC; c++) {
                p[c] = expf(logit[c] - m);
                sum += p[c];
            }
            float inv = __fdiv_rn(1.0f, sum);
            int   am   = 0;
            float best = -INFINITY;
            #pragma unroll
            for (int c = 0; c < CC; c++) {
                p[c] = __fmul_rn(p[c], inv);
                o_probs[idx * CC + c] = p[c];
                if (p[c] > best) { best = p[c]; am = c; }
            }
            g_amax[idx]  = (signed char)am;
            g_score[idx] = best;
            // prep owns keep for amax==0 boxes (never kept)
            if (am == 0) o_keep[idx] = 0.0f;
        }
        // signal
        __syncthreads();
        __threadfence();
        if (tid == 0) atomicAdd(&g_done, 1);
        return;
    }

    // ------------------------- group (consumer) -------------------------
    int b   = blockIdx.x / (CC - 1);
    int cls = 1 + blockIdx.x % (CC - 1);

    unsigned long long* keys = (unsigned long long*)sbuf;

    if (tid == 0) s_count = 0;
    // pre-spin work: zero worst-case bitmask region
    for (int t = tid; t < MAXM * WMAX; t += THREADS) maskbuf[t] = 0;

    // wait for producers
    if (tid == 0) {
        volatile int* dp = &g_done;
        while (*dp < PREP_BLOCKS) __nanosleep(64);
    }
    __syncthreads();
    __threadfence();   // acquire ordering after observing the release

    // gather: coalesced byte loads of amax; rare predicated score load
    for (int n = tid; n < NN; n += THREADS) {
        if ((int)g_amax[b * NN + n] == cls) {
            int pos = atomicAdd(&s_count, 1);
            unsigned int sb = __float_as_uint(g_score[b * NN + n]);
            keys[pos] = ((unsigned long long)sb << 32)
                      | (unsigned long long)(0xFFFFFFFFu - (unsigned)n);
        }
    }
    __syncthreads();
    int M = s_count;
    if (M == 0) return;

    if (M <= MAXM) {
        float4* tlbr = (float4*)(sbuf + 4096);
        float*  area = (float*)(sbuf + 9216);
        int*    sidx = (int*)(sbuf + 10496);
        unsigned int* keptw = (unsigned int*)(sbuf + 11776);
        const int W = (M + 31) >> 5;

        // rank sort (keys unique)
        unsigned long long myk; int myrank = -1;
        if (tid < M) {
            myk = keys[tid];
            int r = 0;
            for (int j = 0; j < M; j++) r += (keys[j] > myk);
            myrank = r;
        }
        __syncthreads();
        if (myrank >= 0) keys[myrank] = myk;
        __syncthreads();

        // stage: one LDG.128 per candidate
        if (tid < M) {
            int n = (int)(0xFFFFFFFFu - (unsigned)(keys[tid] & 0xFFFFFFFFu));
            sidx[tid] = n;
            float4 v = g_box[b * NN + n];
            tlbr[tid] = v;
            area[tid] = __fmul_rn(fmaxf(__fsub_rn(v.z, v.x), 0.0f),
                                  fmaxf(__fsub_rn(v.w, v.y), 0.0f));
        }
        __syncthreads();

        // suppression matrix: thread owns cell (row i, word w) -> no atomics
        int ncells = M * W;
        for (int t = tid; t < ncells; t += THREADS) {
            int i = t / W;
            int w = t - i * W;
            int jbase = w << 5;
            if (jbase + 31 <= i) continue;            // entire word is j<=i
            float4 bi = tlbr[i];
            float  ai = area[i];
            unsigned int word = 0;
            #pragma unroll 4
            for (int bit = 0; bit < 32; bit++) {
                int j = jbase + bit;
                if (j > i && j < M) {
                    float4 bj = tlbr[j];
                    float ih = fmaxf(__fsub_rn(fminf(bi.z, bj.z), fmaxf(bi.x, bj.x)), 0.0f);
                    float iw = fmaxf(__fsub_rn(fminf(bi.w, bj.w), fmaxf(bi.y, bj.y)), 0.0f);
                    float inter = __fmul_rn(ih, iw);
                    float uni   = __fsub_rn(__fadd_rn(ai, area[j]), inter);
                    float iou   = __fdiv_rn(inter, fmaxf(uni, 1e-9f));
                    if (iou > 0.5f) word |= (1u << bit);
                }
            }
            maskbuf[i * W + w] = word;
        }
        __syncthreads();

        // warp 0: branchless chunked greedy scan
        if (tid < 32) {
            unsigned int R = 0u, K = 0u;
            int ldslane = (lane < W) ? lane : (W - 1);
            unsigned int lanemask = (lane < W) ? 0xFFFFFFFFu : 0u;
            for (int c = 0; c < W; c++) {
                unsigned int curw = __shfl_sync(0xFFFFFFFFu, R, c);
                int ibase = c << 5;
                #pragma unroll 8
                for (int bit = 0; bit < 32; bit++) {
                    int i = ibase + bit;
                    unsigned int valid = (i < M) ? 0xFFFFFFFFu : 0u;
                    unsigned int keptm = (~(curw >> bit) & 1u) ? valid : 0u;
                    unsigned int mwc = maskbuf[i * W + c]       & valid;
                    unsigned int mwl = maskbuf[i * W + ldslane] & lanemask & valid;
                    curw |= (mwc & keptm);
                    R    |= (mwl & keptm);
                    K    |= ((lane == c) ? (keptm & (1u << bit)) : 0u);
                }
            }
            if (lane < W) keptw[lane] = K;
        }
        __syncthreads();

        // write keep (0/1) for owned candidates; in-batch index 0 never kept.
        if (tid < M) {
            int n = sidx[tid];
            bool kept = (keptw[tid >> 5] >> (tid & 31)) & 1u;
            o_keep[b * NN + n] = (kept && n != 0) ? 1.0f : 0.0f;
        }
    } else {
        // -------- fallback (statistically unreachable; M > 320) --------
        int P = 1;
        while (P < M) P <<= 1;
        for (int i = M + tid; i < P; i += THREADS) keys[i] = 0ULL;
        __syncthreads();
        for (int k = 2; k <= P; k <<= 1) {
            for (int j = k >> 1; j > 0; j >>= 1) {
                for (int i = tid; i < P; i += THREADS) {
                    int ixj = i ^ j;
                    if (ixj > i) {
                        unsigned long long a = keys[i];
                        unsigned long long c = keys[ixj];
                        bool dirDesc = ((i & k) == 0);
                        if ((a < c) == dirDesc) { keys[i] = c; keys[ixj] = a; }
                    }
                }
                __syncthreads();
            }
        }
        unsigned char* st = (unsigned char*)maskbuf;   // 0=alive 1=suppressed 2=kept
        for (int i = tid; i < M; i += THREADS) st[i] = 0;
        __syncthreads();
        for (int i = 0; i < M; i++) {
            if (st[i] == 0) {
                int ni = (int)(0xFFFFFFFFu - (unsigned)(keys[i] & 0xFFFFFFFFu));
                float4 vi = g_box[b * NN + ni];
                float ai = __fmul_rn(fmaxf(__fsub_rn(vi.z, vi.x), 0.0f),
                                     fmaxf(__fsub_rn(vi.w, vi.y), 0.0f));
                if (tid == 0) st[i] = 2;
                for (int j = i + 1 + tid; j < M; j += THREADS) {
                    if (st[j]) continue;
                    int nj = (int)(0xFFFFFFFFu - (unsigned)(keys[j] & 0xFFFFFFFFu));
                    float4 vj = g_box[b * NN + nj];
                    float aj = __fmul_rn(fmaxf(__fsub_rn(vj.z, vj.x), 0.0f),
                                         fmaxf(__fsub_rn(vj.w, vj.y), 0.0f));
                    float ih = fmaxf(__fsub_rn(fminf(vi.z, vj.z), fmaxf(vi.x, vj.x)), 0.0f);
                    float iw = fmaxf(__fsub_rn(fminf(vi.w, vj.w), fmaxf(vi.y, vj.y)), 0.0f);
                    float inter = __fmul_rn(ih, iw);
                    float uni   = __fsub_rn(__fadd_rn(ai, aj), inter);
                    float iou   = __fdiv_rn(inter, fmaxf(uni, 1e-9f));
                    if (iou > 0.5f) st[j] = 1;
                }
            }
            __syncthreads();
        }
        for (int i = tid; i < M; i += THREADS) {
            int n = (int)(0xFFFFFFFFu - (unsigned)(keys[i] & 0xFFFFFFFFu));
            o_keep[b * NN + n] = (st[i] == 2 && n != 0) ? 1.0f : 0.0f;
        }
    }
}

extern "C" void kernel_launch(void* const* d_in, const int* in_sizes, int n_in,
                              void* d_out, int out_size)
{
    const float* nms_reg  = (const float*)d_in[0];
    const float* nms_cls  = (const float*)d_in[1];
    const float* rcnn_reg = (const float*)d_in[2];
    const float* rcnn_cls = (const float*)d_in[3];
    const unsigned int* red = (const unsigned int*)d_in[4];
    float* out = (float*)d_out;

    reset_kernel<<<1, 1>>>();
    fused_kernel<<<NGROUPS + PREP_BLOCKS, THREADS>>>(
        nms_reg, nms_cls, rcnn_reg, rcnn_cls, red, out);
}